// round 13
// baseline (speedup 1.0000x reference)
#include <cuda_runtime.h>
#include <cuda_fp16.h>
#include <cstdint>

#define N_NODES  50000
#define N_EDGES  800000
#define HID      96
#define OUT_DIM  32
#define N_GRAPHS 256
#define CAP      64                      // bucket capacity per node (E/N=16, max~35)
#define HALF_N   25088                   // split point (multiple of 128)

// ---------------- scratch (static device globals; no allocation) ----------------
__device__ __align__(128) float  g_dis[N_NODES];           // d^{-1/2}
__device__ __align__(128) __half g_tmpA[N_NODES * HID];    // h @ W (UNscaled), fp16, ping
__device__ __align__(128) __half g_tmpB[N_NODES * HID];    // pong
__device__ __align__(128) __half g_bufA[N_NODES * HID];    // layer outputs (ping), fp16
__device__ __align__(128) __half g_bufB[N_NODES * HID];    // layer outputs (pong), fp16
__device__ __align__(128) float  g_pool[N_GRAPHS * HID];
__device__ __align__(128) float  g_cnt [N_GRAPHS];
// bucketed adjacency: node c owns slots [c*CAP, c*CAP + deg)
// after pack_kernel: word = src_idx (low 16) | half_bits(dis[src]) (high 16)
__device__ __align__(128) unsigned int g_cursor[N_NODES];
__device__ __align__(128) unsigned int g_srcs  [N_NODES * CAP];   // 12.8 MB

__device__ __forceinline__ __half* buf_ptr(int sel) {
    return (sel == 1) ? g_bufA : g_bufB;
}
__device__ __forceinline__ __half* tmp_ptr(int sel) {
    return (sel == 0) ? g_tmpA : g_tmpB;
}

__device__ __forceinline__ float to_tf32(float x) {
    uint32_t r;
    asm("cvt.rna.tf32.f32 %0, %1;" : "=r"(r) : "f"(x));
    return __uint_as_float(r);
}

// ---------------- 1a. init cursor to bucket base (critical path) ----------------
__global__ void zero_cursor_kernel() {
    int i = blockIdx.x * blockDim.x + threadIdx.x;
    if (i < N_NODES) g_cursor[i] = i * CAP;
}

// ---------------- 1b. zero pool/cnt (side stream; only needed by gather-3) ----------------
__global__ void zero_pool_kernel() {
    int i = blockIdx.x * blockDim.x + threadIdx.x;
    if (i < N_GRAPHS * HID) g_pool[i] = 0.0f;
    if (i < N_GRAPHS) g_cnt[i] = 0.0f;
}

// ---------------- 2. fill buckets directly (4 edges/thread) ----------------
__global__ void fill_kernel(const int* __restrict__ row, const int* __restrict__ col) {
    int i = blockIdx.x * blockDim.x + threadIdx.x;
    if (i >= N_EDGES / 4) return;
    int4 r = ((const int4*)row)[i];
    int4 c = ((const int4*)col)[i];
    unsigned int p;
    p = atomicAdd(&g_cursor[c.x], 1u); if (p < (unsigned)(c.x * CAP + CAP)) g_srcs[p] = r.x;
    p = atomicAdd(&g_cursor[c.y], 1u); if (p < (unsigned)(c.y * CAP + CAP)) g_srcs[p] = r.y;
    p = atomicAdd(&g_cursor[c.z], 1u); if (p < (unsigned)(c.z * CAP + CAP)) g_srcs[p] = r.z;
    p = atomicAdd(&g_cursor[c.w], 1u); if (p < (unsigned)(c.w * CAP + CAP)) g_srcs[p] = r.w;
}

// ---------------- 3. dis = rsqrt(1 + deg); clamp cursor ----------------
__global__ void dis_kernel() {
    int i = blockIdx.x * blockDim.x + threadIdx.x;
    if (i >= N_NODES) return;
    unsigned int cur = g_cursor[i];
    int deg = (int)cur - i * CAP;
    if (deg > CAP) { deg = CAP; g_cursor[i] = i * CAP + CAP; }
    g_dis[i] = rsqrtf(1.0f + (float)deg);
}

// ---------------- 3b. pack src + dis[src](fp16) into bucket words ----------------
__global__ __launch_bounds__(256) void pack_kernel() {
    int n    = (blockIdx.x * blockDim.x + threadIdx.x) >> 5;
    int lane = threadIdx.x & 31;
    if (n >= N_NODES) return;
    unsigned int end = g_cursor[n];
    for (unsigned int s = n * CAP + lane; s < end; s += 32) {
        unsigned int r = g_srcs[s];                 // plain index (< 65536)
        unsigned short hb = __half_as_ushort(__float2half(g_dis[r]));
        g_srcs[s] = r | ((unsigned int)hb << 16);
    }
}

// ---------------- 4. tf32 MMA GEMM: tmp(fp16) = act(in) @ W  (half-range capable) ----------------
#define GMT 256
#define GMR 128
#define SST 104                                       // smem row stride (floats)
#define GEMM_SMEM ((HID + GMR) * SST * 4)             // 93184 B
__global__ __launch_bounds__(GMT) void gemm_kernel(
    const float* __restrict__ xin, int in_sel,
    const float* __restrict__ W, int tmp_sel, int row_base)
{
    extern __shared__ float smem[];
    float* Ws = smem;              // [96][104]
    float* hs = smem + HID * SST;  // [128][104]

    const int tid = threadIdx.x;
    const int r0  = row_base + blockIdx.x * GMR;

    #pragma unroll
    for (int i4 = tid; i4 < HID * (HID / 4); i4 += GMT) {
        int r = i4 / (HID / 4), c4 = i4 % (HID / 4);
        float4 v = ((const float4*)W)[i4];
        float* d = Ws + r * SST + c4 * 4;
        d[0] = to_tf32(v.x); d[1] = to_tf32(v.y);
        d[2] = to_tf32(v.z); d[3] = to_tf32(v.w);
    }
    if (in_sel == 0) {
        #pragma unroll
        for (int i4 = tid; i4 < GMR * (HID / 4); i4 += GMT) {
            int r = i4 / (HID / 4), c4 = i4 % (HID / 4);
            float4 v = make_float4(0.f, 0.f, 0.f, 0.f);
            if (r0 + r < N_NODES) v = ((const float4*)(xin + (size_t)(r0 + r) * HID))[c4];
            float* d = hs + r * SST + c4 * 4;
            d[0] = to_tf32(v.x); d[1] = to_tf32(v.y);
            d[2] = to_tf32(v.z); d[3] = to_tf32(v.w);
        }
    } else {
        const __half* in = buf_ptr(in_sel);
        #pragma unroll
        for (int i4 = tid; i4 < GMR * (HID / 4); i4 += GMT) {
            int r = i4 / (HID / 4), c4 = i4 % (HID / 4);
            float4 v = make_float4(0.f, 0.f, 0.f, 0.f);
            if (r0 + r < N_NODES) {
                uint2 h = ((const uint2*)(in + (size_t)(r0 + r) * HID))[c4];
                float2 f0 = __half22float2(*(const __half2*)&h.x);
                float2 f1 = __half22float2(*(const __half2*)&h.y);
                v = make_float4(f0.x, f0.y, f1.x, f1.y);
            }
            v.x = fmaxf(v.x, 0.f); v.y = fmaxf(v.y, 0.f);   // relu (hidden layers)
            v.z = fmaxf(v.z, 0.f); v.w = fmaxf(v.w, 0.f);
            float* d = hs + r * SST + c4 * 4;
            d[0] = to_tf32(v.x); d[1] = to_tf32(v.y);
            d[2] = to_tf32(v.z); d[3] = to_tf32(v.w);
        }
    }
    __syncthreads();

    const int warp = tid >> 5;
    const int lane = tid & 31;
    const int gID  = lane >> 2;
    const int tig  = lane & 3;
    const int wm   = warp * 16;

    float c[12][4];
    #pragma unroll
    for (int j = 0; j < 12; j++)
        #pragma unroll
        for (int q = 0; q < 4; q++) c[j][q] = 0.0f;

    #pragma unroll
    for (int k0 = 0; k0 < HID; k0 += 8) {
        const float* ha = hs + (wm + gID) * SST + k0 + tig;
        uint32_t a0 = __float_as_uint(ha[0]);
        uint32_t a1 = __float_as_uint(ha[8 * SST]);
        uint32_t a2 = __float_as_uint(ha[4]);
        uint32_t a3 = __float_as_uint(ha[8 * SST + 4]);
        const float* wb0 = Ws + (k0 + tig) * SST + gID;
        #pragma unroll
        for (int j = 0; j < 12; j++) {
            uint32_t b0 = __float_as_uint(wb0[j * 8]);
            uint32_t b1 = __float_as_uint(wb0[j * 8 + 4 * SST]);
            asm volatile(
                "mma.sync.aligned.m16n8k8.row.col.f32.tf32.tf32.f32 "
                "{%0,%1,%2,%3}, {%4,%5,%6,%7}, {%8,%9}, {%0,%1,%2,%3};"
                : "+f"(c[j][0]), "+f"(c[j][1]), "+f"(c[j][2]), "+f"(c[j][3])
                : "r"(a0), "r"(a1), "r"(a2), "r"(a3), "r"(b0), "r"(b1));
        }
    }

    __half* tp = tmp_ptr(tmp_sel);
    int row0 = r0 + wm + gID;
    int row1 = row0 + 8;
    #pragma unroll
    for (int j = 0; j < 12; j++) {
        int col = j * 8 + tig * 2;
        if (row0 < N_NODES)
            *(__half2*)(tp + (size_t)row0 * HID + col) =
                __floats2half2_rn(c[j][0], c[j][1]);
        if (row1 < N_NODES)
            *(__half2*)(tp + (size_t)row1 * HID + col) =
                __floats2half2_rn(c[j][2], c[j][3]);
    }
}

// ---------------- 5. gather (half-range capable) ----------------
__device__ __forceinline__ void acc_fma(float4& a, uint2 v, float s) {
    float2 f0 = __half22float2(*(const __half2*)&v.x);
    float2 f1 = __half22float2(*(const __half2*)&v.y);
    a.x = fmaf(f0.x, s, a.x); a.y = fmaf(f0.y, s, a.y);
    a.z = fmaf(f1.x, s, a.z); a.w = fmaf(f1.y, s, a.w);
}

__global__ __launch_bounds__(256) void gather_kernel(
    const float* __restrict__ b, int tmp_sel, int out_sel,
    const int* __restrict__ batch, int node_base)
{
    int c    = node_base + ((blockIdx.x * blockDim.x + threadIdx.x) >> 5);
    int lane = threadIdx.x & 31;
    if (c >= N_NODES) return;

    int g = 0;
    if (batch) g = batch[c];
    if (lane >= 24) {
        if (batch && lane == 24) atomicAdd(&g_cnt[g], 1.0f);
        return;
    }

    unsigned int beg = c * CAP;
    unsigned int end = g_cursor[c];
    float dc = g_dis[c];

    const uint2* T = (const uint2*)tmp_ptr(tmp_sel);   // row r = T[r*24 .. r*24+23]
    float4 acc0 = make_float4(0.f, 0.f, 0.f, 0.f);
    float4 acc1 = make_float4(0.f, 0.f, 0.f, 0.f);
    acc_fma(acc0, T[c * 24 + lane], dc);    // self term

    unsigned int e = beg;
    for (; e + 8 <= end; e += 8) {
        uint4 q0 = *(const uint4*)&g_srcs[e];       // broadcast LDG.128
        uint4 q1 = *(const uint4*)&g_srcs[e + 4];
        unsigned int p[8] = {q0.x, q0.y, q0.z, q0.w, q1.x, q1.y, q1.z, q1.w};
        uint2 v[8];
        float s[8];
        #pragma unroll
        for (int i = 0; i < 8; i++) {
            int r = (int)(p[i] & 0xFFFFu);
            s[i] = __half2float(__ushort_as_half((unsigned short)(p[i] >> 16)));
            v[i] = T[r * 24 + lane];
        }
        #pragma unroll
        for (int i = 0; i < 8; i += 2) {
            acc_fma(acc0, v[i], s[i]);
            acc_fma(acc1, v[i + 1], s[i + 1]);
        }
    }
    for (; e < end; e++) {
        unsigned int p = __ldg(&g_srcs[e]);
        int   r = (int)(p & 0xFFFFu);
        float si = __half2float(__ushort_as_half((unsigned short)(p >> 16)));
        acc_fma(acc0, T[r * 24 + lane], si);
    }
    acc0.x += acc1.x; acc0.y += acc1.y; acc0.z += acc1.z; acc0.w += acc1.w;

    float4 bb = ((const float4*)b)[lane];
    float4 o  = make_float4(bb.x + dc * acc0.x, bb.y + dc * acc0.y,
                            bb.z + dc * acc0.z, bb.w + dc * acc0.w);
    if (!batch) {
        __half2 h0 = __floats2half2_rn(o.x, o.y);
        __half2 h1 = __floats2half2_rn(o.z, o.w);
        uint2 hw;
        hw.x = *(const unsigned int*)&h0;
        hw.y = *(const unsigned int*)&h1;
        ((uint2*)buf_ptr(out_sel))[c * 24 + lane] = hw;
    } else {
        float* dst = g_pool + g * HID + lane * 4;
        atomicAdd(dst + 0, fmaxf(o.x, 0.0f));
        atomicAdd(dst + 1, fmaxf(o.y, 0.0f));
        atomicAdd(dst + 2, fmaxf(o.z, 0.0f));
        atomicAdd(dst + 3, fmaxf(o.w, 0.0f));
    }
}

// ---------------- 6. final: out = (pool / max(cnt,1)) @ fc_w + fc_b ----------------
__global__ __launch_bounds__(256) void final_kernel(
    const float* __restrict__ fc_w, const float* __restrict__ fc_b,
    float* __restrict__ out)
{
    int t = blockIdx.x * blockDim.x + threadIdx.x;   // 8192
    if (t >= N_GRAPHS * OUT_DIM) return;
    int g = t >> 5;
    int o = t & 31;
    float inv = 1.0f / fmaxf(g_cnt[g], 1.0f);
    float acc = fc_b[o];
    #pragma unroll 8
    for (int f = 0; f < HID; f++)
        acc = fmaf(g_pool[g * HID + f] * inv, fc_w[f * OUT_DIM + o], acc);
    out[t] = acc;
}

// ---------------- launch ----------------
extern "C" void kernel_launch(void* const* d_in, const int* in_sizes, int n_in,
                              void* d_out, int out_size)
{
    const float* x    = (const float*)d_in[0];
    const int*   ei   = (const int*)d_in[1];   // [2, E] int32
    const int*   bat  = (const int*)d_in[2];   // [N] int32
    const float* W1   = (const float*)d_in[3];
    const float* b1   = (const float*)d_in[4];
    const float* W2   = (const float*)d_in[5];
    const float* b2   = (const float*)d_in[6];
    const float* W3   = (const float*)d_in[7];
    const float* b3   = (const float*)d_in[8];
    const float* fc_w = (const float*)d_in[9];
    const float* fc_b = (const float*)d_in[10];
    float* out = (float*)d_out;

    const int* erow = ei;
    const int* ecol = ei + N_EDGES;

    static cudaStream_t s_side = nullptr;
    static cudaEvent_t  ev1, ev2, evG1a, evM2a, evG2a, evM3a;
    if (!s_side) {
        cudaFuncSetAttribute(gemm_kernel,
                             cudaFuncAttributeMaxDynamicSharedMemorySize, GEMM_SMEM);
        cudaStreamCreateWithFlags(&s_side, cudaStreamNonBlocking);
        cudaEventCreateWithFlags(&ev1,   cudaEventDisableTiming);
        cudaEventCreateWithFlags(&ev2,   cudaEventDisableTiming);
        cudaEventCreateWithFlags(&evG1a, cudaEventDisableTiming);
        cudaEventCreateWithFlags(&evM2a, cudaEventDisableTiming);
        cudaEventCreateWithFlags(&evG2a, cudaEventDisableTiming);
        cudaEventCreateWithFlags(&evM3a, cudaEventDisableTiming);
    }

    const int gemm_grid   = (N_NODES + GMR - 1) / GMR;        // 391 (full)
    const int gemm_gridA  = HALF_N / GMR;                     // 196
    const int gemm_gridB  = (N_NODES - HALF_N + GMR - 1) / GMR;  // 195
    const int gwA         = (HALF_N * 32 + 255) / 256;        // 3136
    const int gwB         = ((N_NODES - HALF_N) * 32 + 255) / 256;
    const int node_warps  = (N_NODES * 32 + 255) / 256;
    const int e4_grid     = (N_EDGES / 4 + 255) / 256;

    // fork: gemm1(full -> tmpA) + pool-zero on side stream (independent of build)
    cudaEventRecord(ev1, 0);
    cudaStreamWaitEvent(s_side, ev1, 0);
    gemm_kernel<<<gemm_grid, GMT, GEMM_SMEM, s_side>>>(x, 0, W1, 0, 0);
    zero_pool_kernel<<<(N_GRAPHS * HID + 255) / 256, 256, 0, s_side>>>();
    cudaEventRecord(ev2, s_side);

    // bucketed adjacency build on main stream
    zero_cursor_kernel<<<(N_NODES + 255) / 256, 256>>>();
    fill_kernel<<<e4_grid, 256>>>(erow, ecol);
    dis_kernel<<<(N_NODES + 255) / 256, 256>>>();
    pack_kernel<<<node_warps, 256>>>();
    cudaStreamWaitEvent(0, ev2, 0);

    // ---- layer 1 gather (tmpA -> bufA), split ----
    gather_kernel<<<gwA, 256>>>(b1, 0, 1, nullptr, 0);
    cudaEventRecord(evG1a, 0);
    gather_kernel<<<gwB, 256>>>(b1, 0, 1, nullptr, HALF_N);

    // gemm2 half A (bufA[0,H) -> tmpB[0,H)) overlapped on side stream
    cudaStreamWaitEvent(s_side, evG1a, 0);
    gemm_kernel<<<gemm_gridA, GMT, GEMM_SMEM, s_side>>>(nullptr, 1, W2, 1, 0);
    cudaEventRecord(evM2a, s_side);
    // gemm2 half B on main (after gather1 half B)
    gemm_kernel<<<gemm_gridB, GMT, GEMM_SMEM>>>(nullptr, 1, W2, 1, HALF_N);
    cudaStreamWaitEvent(0, evM2a, 0);

    // ---- layer 2 gather (tmpB -> bufB), split ----
    gather_kernel<<<gwA, 256>>>(b2, 1, 2, nullptr, 0);
    cudaEventRecord(evG2a, 0);
    gather_kernel<<<gwB, 256>>>(b2, 1, 2, nullptr, HALF_N);

    // gemm3 half A (bufB[0,H) -> tmpA[0,H)) overlapped on side stream
    cudaStreamWaitEvent(s_side, evG2a, 0);
    gemm_kernel<<<gemm_gridA, GMT, GEMM_SMEM, s_side>>>(nullptr, 2, W3, 0, 0);
    cudaEventRecord(evM3a, s_side);
    // gemm3 half B on main
    gemm_kernel<<<gemm_gridB, GMT, GEMM_SMEM>>>(nullptr, 2, W3, 0, HALF_N);
    cudaStreamWaitEvent(0, evM3a, 0);

    // ---- layer 3 gather (tmpA -> pool, fused relu+pool) ----
    gather_kernel<<<gwA, 256>>>(b3, 0, 0, bat, 0);
    gather_kernel<<<gwB, 256>>>(b3, 0, 0, bat, HALF_N);

    // FC
    final_kernel<<<(N_GRAPHS * OUT_DIM + 255) / 256, 256>>>(fc_w, fc_b, out);
}

// round 15
// speedup vs baseline: 1.1484x; 1.1484x over previous
#include <cuda_runtime.h>
#include <cuda_fp16.h>
#include <cstdint>

#define N_NODES  50000
#define N_EDGES  800000
#define HID      96
#define OUT_DIM  32
#define N_GRAPHS 256
#define CAP      64                      // bucket capacity per node (E/N=16, max~35)

// ---------------- scratch (static device globals; no allocation) ----------------
__device__ __align__(128) float  g_dis[N_NODES];           // d^{-1/2}
__device__ __align__(128) __half g_tmp [N_NODES * HID];    // h @ W (UNscaled), fp16
__device__ __align__(128) __half g_bufA[N_NODES * HID];    // layer outputs (ping), fp16
__device__ __align__(128) __half g_bufB[N_NODES * HID];    // layer outputs (pong), fp16
__device__ __align__(128) float  g_pool[N_GRAPHS * HID];
__device__ __align__(128) float  g_cnt [N_GRAPHS];
// bucketed adjacency: node c owns slots [c*CAP, c*CAP + deg)
// after pack_kernel: word = src_idx (low 16) | half_bits(dis[src]) (high 16)
__device__ __align__(128) unsigned int g_cursor[N_NODES];
__device__ __align__(128) unsigned int g_srcs  [N_NODES * CAP];   // 12.8 MB

__device__ __forceinline__ __half* buf_ptr(int sel) {
    return (sel == 1) ? g_bufA : g_bufB;
}

__device__ __forceinline__ float to_tf32(float x) {
    uint32_t r;
    asm("cvt.rna.tf32.f32 %0, %1;" : "=r"(r) : "f"(x));
    return __uint_as_float(r);
}

// ---------------- 1. init cursor to bucket base + zero pool/cnt (one kernel) ----------------
__global__ void zero_kernel() {
    int i = blockIdx.x * blockDim.x + threadIdx.x;
    if (i < N_NODES) g_cursor[i] = i * CAP;
    if (i < N_GRAPHS * HID) g_pool[i] = 0.0f;
    if (i < N_GRAPHS) g_cnt[i] = 0.0f;
}

// ---------------- 2. fill buckets directly (4 edges/thread) ----------------
__global__ void fill_kernel(const int* __restrict__ row, const int* __restrict__ col) {
    int i = blockIdx.x * blockDim.x + threadIdx.x;
    if (i >= N_EDGES / 4) return;
    int4 r = ((const int4*)row)[i];
    int4 c = ((const int4*)col)[i];
    unsigned int p;
    p = atomicAdd(&g_cursor[c.x], 1u); if (p < (unsigned)(c.x * CAP + CAP)) g_srcs[p] = r.x;
    p = atomicAdd(&g_cursor[c.y], 1u); if (p < (unsigned)(c.y * CAP + CAP)) g_srcs[p] = r.y;
    p = atomicAdd(&g_cursor[c.z], 1u); if (p < (unsigned)(c.z * CAP + CAP)) g_srcs[p] = r.z;
    p = atomicAdd(&g_cursor[c.w], 1u); if (p < (unsigned)(c.w * CAP + CAP)) g_srcs[p] = r.w;
}

// ---------------- 3. dis = rsqrt(1 + deg); clamp cursor ----------------
__global__ void dis_kernel() {
    int i = blockIdx.x * blockDim.x + threadIdx.x;
    if (i >= N_NODES) return;
    unsigned int cur = g_cursor[i];
    int deg = (int)cur - i * CAP;
    if (deg > CAP) { deg = CAP; g_cursor[i] = i * CAP + CAP; }
    g_dis[i] = rsqrtf(1.0f + (float)deg);
}

// ---------------- 3b. pack src + dis[src](fp16) into bucket words ----------------
__global__ __launch_bounds__(256) void pack_kernel() {
    int n    = (blockIdx.x * blockDim.x + threadIdx.x) >> 5;
    int lane = threadIdx.x & 31;
    if (n >= N_NODES) return;
    unsigned int end = g_cursor[n];
    for (unsigned int s = n * CAP + lane; s < end; s += 32) {
        unsigned int r = g_srcs[s];                 // plain index (< 65536)
        unsigned short hb = __half_as_ushort(__float2half(g_dis[r]));
        g_srcs[s] = r | ((unsigned int)hb << 16);
    }
}

// ---------------- 4. tf32 MMA GEMM: tmp(fp16) = act(in) @ W ----------------
#define GMT 256
#define GMR 128
#define SST 104                                       // smem row stride (floats)
#define GEMM_SMEM ((HID + GMR) * SST * 4)             // 93184 B
__global__ __launch_bounds__(GMT) void gemm_kernel(
    const float* __restrict__ xin, int in_sel,
    const float* __restrict__ W, int relu_in)
{
    extern __shared__ float smem[];
    float* Ws = smem;              // [96][104]
    float* hs = smem + HID * SST;  // [128][104]

    const int tid = threadIdx.x;
    const int r0  = blockIdx.x * GMR;

    #pragma unroll
    for (int i4 = tid; i4 < HID * (HID / 4); i4 += GMT) {
        int r = i4 / (HID / 4), c4 = i4 % (HID / 4);
        float4 v = ((const float4*)W)[i4];
        float* d = Ws + r * SST + c4 * 4;
        d[0] = to_tf32(v.x); d[1] = to_tf32(v.y);
        d[2] = to_tf32(v.z); d[3] = to_tf32(v.w);
    }
    if (in_sel == 0) {
        #pragma unroll
        for (int i4 = tid; i4 < GMR * (HID / 4); i4 += GMT) {
            int r = i4 / (HID / 4), c4 = i4 % (HID / 4);
            float4 v = make_float4(0.f, 0.f, 0.f, 0.f);
            if (r0 + r < N_NODES) v = ((const float4*)(xin + (size_t)(r0 + r) * HID))[c4];
            float* d = hs + r * SST + c4 * 4;
            d[0] = to_tf32(v.x); d[1] = to_tf32(v.y);
            d[2] = to_tf32(v.z); d[3] = to_tf32(v.w);
        }
    } else {
        const __half* in = buf_ptr(in_sel);
        #pragma unroll
        for (int i4 = tid; i4 < GMR * (HID / 4); i4 += GMT) {
            int r = i4 / (HID / 4), c4 = i4 % (HID / 4);
            float4 v = make_float4(0.f, 0.f, 0.f, 0.f);
            if (r0 + r < N_NODES) {
                uint2 h = ((const uint2*)(in + (size_t)(r0 + r) * HID))[c4];
                float2 f0 = __half22float2(*(const __half2*)&h.x);
                float2 f1 = __half22float2(*(const __half2*)&h.y);
                v = make_float4(f0.x, f0.y, f1.x, f1.y);
            }
            v.x = fmaxf(v.x, 0.f); v.y = fmaxf(v.y, 0.f);   // relu (hidden layers)
            v.z = fmaxf(v.z, 0.f); v.w = fmaxf(v.w, 0.f);
            float* d = hs + r * SST + c4 * 4;
            d[0] = to_tf32(v.x); d[1] = to_tf32(v.y);
            d[2] = to_tf32(v.z); d[3] = to_tf32(v.w);
        }
    }
    __syncthreads();

    const int warp = tid >> 5;
    const int lane = tid & 31;
    const int gID  = lane >> 2;
    const int tig  = lane & 3;
    const int wm   = warp * 16;

    float c[12][4];
    #pragma unroll
    for (int j = 0; j < 12; j++)
        #pragma unroll
        for (int q = 0; q < 4; q++) c[j][q] = 0.0f;

    #pragma unroll
    for (int k0 = 0; k0 < HID; k0 += 8) {
        const float* ha = hs + (wm + gID) * SST + k0 + tig;
        uint32_t a0 = __float_as_uint(ha[0]);
        uint32_t a1 = __float_as_uint(ha[8 * SST]);
        uint32_t a2 = __float_as_uint(ha[4]);
        uint32_t a3 = __float_as_uint(ha[8 * SST + 4]);
        const float* wb0 = Ws + (k0 + tig) * SST + gID;
        #pragma unroll
        for (int j = 0; j < 12; j++) {
            uint32_t b0 = __float_as_uint(wb0[j * 8]);
            uint32_t b1 = __float_as_uint(wb0[j * 8 + 4 * SST]);
            asm volatile(
                "mma.sync.aligned.m16n8k8.row.col.f32.tf32.tf32.f32 "
                "{%0,%1,%2,%3}, {%4,%5,%6,%7}, {%8,%9}, {%0,%1,%2,%3};"
                : "+f"(c[j][0]), "+f"(c[j][1]), "+f"(c[j][2]), "+f"(c[j][3])
                : "r"(a0), "r"(a1), "r"(a2), "r"(a3), "r"(b0), "r"(b1));
        }
    }

    int row0 = r0 + wm + gID;
    int row1 = row0 + 8;
    #pragma unroll
    for (int j = 0; j < 12; j++) {
        int col = j * 8 + tig * 2;
        if (row0 < N_NODES)
            *(__half2*)(g_tmp + (size_t)row0 * HID + col) =
                __floats2half2_rn(c[j][0], c[j][1]);
        if (row1 < N_NODES)
            *(__half2*)(g_tmp + (size_t)row1 * HID + col) =
                __floats2half2_rn(c[j][2], c[j][3]);
    }
}

// ---------------- 5. gather: out[c] = b + dis[c]*(dis[c]*tmp[c] + sum dis[s]*tmp[s]) ----------------
__device__ __forceinline__ void acc_fma(float4& a, uint2 v, float s) {
    float2 f0 = __half22float2(*(const __half2*)&v.x);
    float2 f1 = __half22float2(*(const __half2*)&v.y);
    a.x = fmaf(f0.x, s, a.x); a.y = fmaf(f0.y, s, a.y);
    a.z = fmaf(f1.x, s, a.z); a.w = fmaf(f1.y, s, a.w);
}

__global__ __launch_bounds__(256) void gather_kernel(
    const float* __restrict__ b, int out_sel, const int* __restrict__ batch)
{
    int c    = (blockIdx.x * blockDim.x + threadIdx.x) >> 5;
    int lane = threadIdx.x & 31;
    if (c >= N_NODES) return;

    int g = 0;
    if (batch) g = batch[c];
    if (lane >= 24) {
        if (batch && lane == 24) atomicAdd(&g_cnt[g], 1.0f);
        return;
    }

    unsigned int beg = c * CAP;
    unsigned int end = g_cursor[c];
    float dc = rsqrtf(1.0f + (float)(end - beg));   // dis[c] from cursor (clamped already)

    const uint2* T = (const uint2*)g_tmp;   // row r = T[r*24 .. r*24+23]
    float4 acc0 = make_float4(0.f, 0.f, 0.f, 0.f);
    float4 acc1 = make_float4(0.f, 0.f, 0.f, 0.f);
    acc_fma(acc0, T[c * 24 + lane], dc);    // self term

    unsigned int e = beg;
    for (; e + 8 <= end; e += 8) {
        uint4 q0 = *(const uint4*)&g_srcs[e];       // broadcast LDG.128
        uint4 q1 = *(const uint4*)&g_srcs[e + 4];
        unsigned int p[8] = {q0.x, q0.y, q0.z, q0.w, q1.x, q1.y, q1.z, q1.w};
        uint2 v[8];
        float s[8];
        #pragma unroll
        for (int i = 0; i < 8; i++) {
            int r = (int)(p[i] & 0xFFFFu);
            s[i] = __half2float(__ushort_as_half((unsigned short)(p[i] >> 16)));
            v[i] = T[r * 24 + lane];
        }
        #pragma unroll
        for (int i = 0; i < 8; i += 2) {
            acc_fma(acc0, v[i], s[i]);
            acc_fma(acc1, v[i + 1], s[i + 1]);
        }
    }
    for (; e < end; e++) {
        unsigned int p = __ldg(&g_srcs[e]);
        int   r = (int)(p & 0xFFFFu);
        float si = __half2float(__ushort_as_half((unsigned short)(p >> 16)));
        acc_fma(acc0, T[r * 24 + lane], si);
    }
    acc0.x += acc1.x; acc0.y += acc1.y; acc0.z += acc1.z; acc0.w += acc1.w;

    float4 bb = ((const float4*)b)[lane];
    float4 o  = make_float4(bb.x + dc * acc0.x, bb.y + dc * acc0.y,
                            bb.z + dc * acc0.z, bb.w + dc * acc0.w);
    if (!batch) {
        __half2 h0 = __floats2half2_rn(o.x, o.y);
        __half2 h1 = __floats2half2_rn(o.z, o.w);
        uint2 hw;
        hw.x = *(const unsigned int*)&h0;
        hw.y = *(const unsigned int*)&h1;
        ((uint2*)buf_ptr(out_sel))[c * 24 + lane] = hw;
    } else {
        float* dst = g_pool + g * HID + lane * 4;
        atomicAdd(dst + 0, fmaxf(o.x, 0.0f));
        atomicAdd(dst + 1, fmaxf(o.y, 0.0f));
        atomicAdd(dst + 2, fmaxf(o.z, 0.0f));
        atomicAdd(dst + 3, fmaxf(o.w, 0.0f));
    }
}

// ---------------- 6. final: out = (pool / max(cnt,1)) @ fc_w + fc_b ----------------
__global__ __launch_bounds__(256) void final_kernel(
    const float* __restrict__ fc_w, const float* __restrict__ fc_b,
    float* __restrict__ out)
{
    int t = blockIdx.x * blockDim.x + threadIdx.x;   // 8192
    if (t >= N_GRAPHS * OUT_DIM) return;
    int g = t >> 5;
    int o = t & 31;
    float inv = 1.0f / fmaxf(g_cnt[g], 1.0f);
    float acc = fc_b[o];
    #pragma unroll 8
    for (int f = 0; f < HID; f++)
        acc = fmaf(g_pool[g * HID + f] * inv, fc_w[f * OUT_DIM + o], acc);
    out[t] = acc;
}

// ---------------- launch ----------------
extern "C" void kernel_launch(void* const* d_in, const int* in_sizes, int n_in,
                              void* d_out, int out_size)
{
    const float* x    = (const float*)d_in[0];
    const int*   ei   = (const int*)d_in[1];   // [2, E] int32
    const int*   bat  = (const int*)d_in[2];   // [N] int32
    const float* W1   = (const float*)d_in[3];
    const float* b1   = (const float*)d_in[4];
    const float* W2   = (const float*)d_in[5];
    const float* b2   = (const float*)d_in[6];
    const float* W3   = (const float*)d_in[7];
    const float* b3   = (const float*)d_in[8];
    const float* fc_w = (const float*)d_in[9];
    const float* fc_b = (const float*)d_in[10];
    float* out = (float*)d_out;

    const int* erow = ei;
    const int* ecol = ei + N_EDGES;

    static cudaStream_t s_side = nullptr;
    static cudaEvent_t  s_ev1 = nullptr, s_ev2 = nullptr;
    if (!s_side) {
        cudaFuncSetAttribute(gemm_kernel,
                             cudaFuncAttributeMaxDynamicSharedMemorySize, GEMM_SMEM);
        cudaStreamCreateWithFlags(&s_side, cudaStreamNonBlocking);
        cudaEventCreateWithFlags(&s_ev1, cudaEventDisableTiming);
        cudaEventCreateWithFlags(&s_ev2, cudaEventDisableTiming);
    }

    const int gemm_grid  = (N_NODES + GMR - 1) / GMR;    // 391
    const int node_warps = (N_NODES * 32 + 255) / 256;
    const int e4_grid    = (N_EDGES / 4 + 255) / 256;

    // fork: gemm1 (independent of adjacency build) on side stream from t=0
    // launch order => ncu -s 5 lands on gather1: gemm1(0) zero(1) fill(2) dis(3) pack(4) gather1(5)
    cudaEventRecord(s_ev1, 0);
    cudaStreamWaitEvent(s_side, s_ev1, 0);
    gemm_kernel<<<gemm_grid, GMT, GEMM_SMEM, s_side>>>(x, 0, W1, 0);
    cudaEventRecord(s_ev2, s_side);

    // bucketed adjacency build on main stream
    zero_kernel<<<(N_NODES + 255) / 256, 256>>>();
    fill_kernel<<<e4_grid, 256>>>(erow, ecol);
    dis_kernel<<<(N_NODES + 255) / 256, 256>>>();
    pack_kernel<<<node_warps, 256>>>();
    cudaStreamWaitEvent(0, s_ev2, 0);

    // layer 1 gather: -> bufA
    gather_kernel<<<node_warps, 256>>>(b1, 1, nullptr);
    // layer 2: relu(bufA) -> bufB
    gemm_kernel<<<gemm_grid, GMT, GEMM_SMEM>>>(nullptr, 1, W2, 1);
    gather_kernel<<<node_warps, 256>>>(b2, 2, nullptr);
    // layer 3: relu(bufB) -> pool (fused)
    gemm_kernel<<<gemm_grid, GMT, GEMM_SMEM>>>(nullptr, 2, W3, 1);
    gather_kernel<<<node_warps, 256>>>(b3, 0, bat);

    // FC
    final_kernel<<<(N_GRAPHS * OUT_DIM + 255) / 256, 256>>>(fc_w, fc_b, out);
}